// round 2
// baseline (speedup 1.0000x reference)
#include <cuda_runtime.h>
#include <math.h>

#define N_ 768
#define CS 384
#define CZ 128
#define NH 12
#define LINW 1152
#define CATW 2112
#define INF_ 100000.0f

// ---------------- device scratch ----------------
__device__ float g_wpack[CS * LINW];
__device__ float g_bpack[LINW];
__device__ float g_pw[NH];
__device__ float g_lin[N_ * LINW];
__device__ float g_qh[N_ * 192];
__device__ float g_khT[192 * N_];
__device__ float g_qpts[N_ * 144];
__device__ float g_kptsT[144 * N_];
__device__ float g_q2[N_ * NH];
__device__ float g_k2T[NH * N_];
__device__ float g_vcatT[480 * N_];
__device__ float g_bias[N_ * N_ * NH];
__device__ float g_cat[N_ * CATW];
__device__ float g_part[3][N_ * CS];

#define MM16(a, b, c)                                                                                   \
  c[0][0]=fmaf(a.x,b.x,c[0][0]); c[0][1]=fmaf(a.x,b.y,c[0][1]); c[0][2]=fmaf(a.x,b.z,c[0][2]); c[0][3]=fmaf(a.x,b.w,c[0][3]); \
  c[1][0]=fmaf(a.y,b.x,c[1][0]); c[1][1]=fmaf(a.y,b.y,c[1][1]); c[1][2]=fmaf(a.y,b.z,c[1][2]); c[1][3]=fmaf(a.y,b.w,c[1][3]); \
  c[2][0]=fmaf(a.z,b.x,c[2][0]); c[2][1]=fmaf(a.z,b.y,c[2][1]); c[2][2]=fmaf(a.z,b.z,c[2][2]); c[2][3]=fmaf(a.z,b.w,c[2][3]); \
  c[3][0]=fmaf(a.w,b.x,c[3][0]); c[3][1]=fmaf(a.w,b.y,c[3][1]); c[3][2]=fmaf(a.w,b.z,c[3][2]); c[3][3]=fmaf(a.w,b.w,c[3][3]);

// ---------------- pack weights ----------------
__global__ void k_pack(const float* wq, const float* wk, const float* wv,
                       const float* wqp, const float* wkp, const float* wvp,
                       const float* bq, const float* bk, const float* bv,
                       const float* bqp, const float* bkp, const float* bvp,
                       const float* hw) {
  int idx = blockIdx.x * 256 + threadIdx.x;
  if (idx < CS * LINW) {
    int i = idx / LINW, j = idx - i * LINW;
    float v;
    if (j < 192)       v = wq[i * 192 + j];
    else if (j < 384)  v = wk[i * 192 + j - 192];
    else if (j < 576)  v = wv[i * 192 + j - 384];
    else if (j < 720)  v = wqp[i * 144 + j - 576];
    else if (j < 864)  v = wkp[i * 144 + j - 720];
    else               v = wvp[i * 288 + j - 864];
    g_wpack[idx] = v;
  }
  if (idx < LINW) {
    int j = idx;
    float v;
    if (j < 192)       v = bq[j];
    else if (j < 384)  v = bk[j - 192];
    else if (j < 576)  v = bv[j - 384];
    else if (j < 720)  v = bqp[j - 576];
    else if (j < 864)  v = bkp[j - 720];
    else               v = bvp[j - 864];
    g_bpack[j] = v;
  }
  if (idx < NH) {
    float h = hw[idx];
    // sqrt(2/(9*4)) * softplus(h)
    g_pw[idx] = 0.23570226039551584f * (fmaxf(h, 0.f) + log1pf(expf(-fabsf(h))));
  }
}

// ---------------- GEMM 1: g_lin = s @ wpack (768x1152, K=384) ----------------
__global__ __launch_bounds__(256) void k_gemm1(const float* __restrict__ A) {
  __shared__ float aT[16][68];
  __shared__ float bT[16][68];
  int m0 = blockIdx.x * 64, n0 = blockIdx.y * 64;
  int t = threadIdx.x;
  int mi = (t & 15) * 4, ni = (t >> 4) * 4;
  float c[4][4] = {};
  for (int kt = 0; kt < 24; ++kt) {
    int k0 = kt * 16;
    __syncthreads();
#pragma unroll
    for (int j = 0; j < 4; ++j) {
      int e = t + j * 256;
      aT[e & 15][e >> 4] = A[(m0 + (e >> 4)) * CS + k0 + (e & 15)];
      bT[e >> 6][e & 63] = g_wpack[(k0 + (e >> 6)) * LINW + n0 + (e & 63)];
    }
    __syncthreads();
#pragma unroll
    for (int kk = 0; kk < 16; ++kk) {
      float4 a = *(const float4*)&aT[kk][mi];
      float4 b = *(const float4*)&bT[kk][ni];
      MM16(a, b, c);
    }
  }
#pragma unroll
  for (int r = 0; r < 4; ++r)
#pragma unroll
    for (int cc = 0; cc < 4; ++cc)
      g_lin[(m0 + mi + r) * LINW + n0 + ni + cc] = c[r][cc];
}

// ---------------- GEMM 2: part[z] = cat @ w_o (768x384, K=2112 split 3) ----------------
__global__ __launch_bounds__(256) void k_gemm2(const float* __restrict__ B) {
  __shared__ float aT[16][68];
  __shared__ float bT[16][68];
  int m0 = blockIdx.x * 64, n0 = blockIdx.y * 64;
  int t = threadIdx.x;
  int mi = (t & 15) * 4, ni = (t >> 4) * 4;
  float c[4][4] = {};
  int kbase = blockIdx.z * 44 * 16;
  for (int kt = 0; kt < 44; ++kt) {
    int k0 = kbase + kt * 16;
    __syncthreads();
#pragma unroll
    for (int j = 0; j < 4; ++j) {
      int e = t + j * 256;
      aT[e & 15][e >> 4] = g_cat[(m0 + (e >> 4)) * CATW + k0 + (e & 15)];
      bT[e >> 6][e & 63] = B[(k0 + (e >> 6)) * CS + n0 + (e & 63)];
    }
    __syncthreads();
#pragma unroll
    for (int kk = 0; kk < 16; ++kk) {
      float4 a = *(const float4*)&aT[kk][mi];
      float4 b = *(const float4*)&bT[kk][ni];
      MM16(a, b, c);
    }
  }
  float* outp = &g_part[blockIdx.z][0];
#pragma unroll
  for (int r = 0; r < 4; ++r)
#pragma unroll
    for (int cc = 0; cc < 4; ++cc)
      outp[(m0 + mi + r) * CS + n0 + ni + cc] = c[r][cc];
}

// ---------------- projection epilogue per residue ----------------
__global__ __launch_bounds__(128) void k_proj(const float* __restrict__ rot,
                                              const float* __restrict__ trans) {
  __shared__ float s2[24];
  int q = blockIdx.x, t = threadIdx.x;
  const float* lin = g_lin + q * LINW;
  if (t < 24) s2[t] = 0.f;
  __syncthreads();
  float R[9], tr[3];
#pragma unroll
  for (int j = 0; j < 9; ++j) R[j] = __ldg(rot + q * 9 + j);
#pragma unroll
  for (int j = 0; j < 3; ++j) tr[j] = __ldg(trans + q * 3 + j);
  for (int i = t; i < 192; i += 128) {
    g_qh[q * 192 + i] = (lin[i] + g_bpack[i]) * 0.25f;  // * sqrt(1/16)
    g_khT[i * N_ + q] = lin[192 + i] + g_bpack[192 + i];
    int h = i >> 4, cc = i & 15;
    g_vcatT[(h * 40 + cc) * N_ + q] = lin[384 + i] + g_bpack[384 + i];
  }
  if (t < 96) {  // q/k points: layout [h][3][4]
    int which = t / 48;  // 0=q, 1=k
    int i = t % 48;
    int h = i >> 2, p = i & 3;
    int base = 576 + which * 144 + h * 12;
    float lx = lin[base + p] + g_bpack[base + p];
    float ly = lin[base + 4 + p] + g_bpack[base + 4 + p];
    float lz = lin[base + 8 + p] + g_bpack[base + 8 + p];
    float gx = R[0] * lx + R[1] * ly + R[2] * lz + tr[0];
    float gy = R[3] * lx + R[4] * ly + R[5] * lz + tr[1];
    float gz = R[6] * lx + R[7] * ly + R[8] * lz + tr[2];
    float n2 = gx * gx + gy * gy + gz * gz;
    if (which == 0) {
      int o = q * 144 + h * 12 + p * 3;
      g_qpts[o] = gx; g_qpts[o + 1] = gy; g_qpts[o + 2] = gz;
      atomicAdd(&s2[h], n2);
    } else {
      int o = (h * 12 + p * 3) * N_ + q;
      g_kptsT[o] = gx; g_kptsT[o + N_] = gy; g_kptsT[o + 2 * N_] = gz;
      atomicAdd(&s2[12 + h], n2);
    }
  }
  if (t < 96) {  // v points: layout [h][3][8]
    int h = t >> 3, p = t & 7;
    int base = 864 + h * 24;
    float lx = lin[base + p] + g_bpack[base + p];
    float ly = lin[base + 8 + p] + g_bpack[base + 8 + p];
    float lz = lin[base + 16 + p] + g_bpack[base + 16 + p];
    float gx = R[0] * lx + R[1] * ly + R[2] * lz + tr[0];
    float gy = R[3] * lx + R[4] * ly + R[5] * lz + tr[1];
    float gz = R[6] * lx + R[7] * ly + R[8] * lz + tr[2];
    int o = (h * 40 + 16 + p * 3) * N_ + q;
    g_vcatT[o] = gx; g_vcatT[o + N_] = gy; g_vcatT[o + 2 * N_] = gz;
  }
  __syncthreads();
  if (t < 12) {
    g_q2[q * 12 + t] = s2[t];
    g_k2T[t * N_ + q] = s2[12 + t];
  }
}

// ---------------- pair bias: g_bias[q*768+k][h] = z . w_b + b_b ----------------
__global__ __launch_bounds__(128) void k_bias(const float* __restrict__ z,
                                              const float* __restrict__ wb,
                                              const float* __restrict__ bb) {
  __shared__ float zsT[32][260];
  __shared__ float wbsT[12][132];
  int t = threadIdx.x;
  int R0 = blockIdx.x * 256;
  for (int i = t; i < 12 * 128; i += 128) {
    int cc = i & 127, h = i >> 7;
    wbsT[h][cc] = __ldg(wb + cc * 12 + h);
  }
  int rg = t & 31, hg = t >> 5;  // 32 row-groups x 4 head-groups
  float acc[8][3] = {};
  for (int cc = 0; cc < 4; ++cc) {
    __syncthreads();
#pragma unroll
    for (int rr = 0; rr < 2; ++rr) {
      int lr = t + rr * 128;
      const float* zp = z + (size_t)(R0 + lr) * 128 + cc * 32;
#pragma unroll
      for (int c4 = 0; c4 < 8; ++c4) {
        float4 v = *(const float4*)(zp + c4 * 4);
        zsT[c4 * 4 + 0][lr] = v.x;
        zsT[c4 * 4 + 1][lr] = v.y;
        zsT[c4 * 4 + 2][lr] = v.z;
        zsT[c4 * 4 + 3][lr] = v.w;
      }
    }
    __syncthreads();
#pragma unroll
    for (int c = 0; c < 32; ++c) {
      float w0 = wbsT[hg * 3 + 0][cc * 32 + c];
      float w1 = wbsT[hg * 3 + 1][cc * 32 + c];
      float w2 = wbsT[hg * 3 + 2][cc * 32 + c];
#pragma unroll
      for (int j = 0; j < 8; ++j) {
        float zv = zsT[c][rg + 32 * j];
        acc[j][0] = fmaf(zv, w0, acc[j][0]);
        acc[j][1] = fmaf(zv, w1, acc[j][1]);
        acc[j][2] = fmaf(zv, w2, acc[j][2]);
      }
    }
  }
  float b0 = __ldg(bb + hg * 3), b1 = __ldg(bb + hg * 3 + 1), b2 = __ldg(bb + hg * 3 + 2);
#pragma unroll
  for (int j = 0; j < 8; ++j) {
    size_t row = (size_t)R0 + rg + 32 * j;
    g_bias[row * 12 + hg * 3 + 0] = acc[j][0] + b0;
    g_bias[row * 12 + hg * 3 + 1] = acc[j][1] + b1;
    g_bias[row * 12 + hg * 3 + 2] = acc[j][2] + b2;
  }
}

// ---------------- fused attention per query row ----------------
__global__ __launch_bounds__(256) void k_attn(const float* __restrict__ z,
                                              const float* __restrict__ mask,
                                              const float* __restrict__ rot,
                                              const float* __restrict__ trans) {
  __shared__ float lgT[12][776];
  __shared__ float qh_s[192], qp_s[144], c0_s[12], cb_s[12], opt_s[288];
  int q = blockIdx.x, t = threadIdx.x;
  for (int i = t; i < 192; i += 256) qh_s[i] = g_qh[q * 192 + i];
  if (t < 144) qp_s[t] = g_qpts[q * 144 + t];
  if (t < 12) {
    float pw = g_pw[t];
    c0_s[t] = pw;
    cb_s[t] = -0.5f * pw * g_q2[q * 12 + t];
  }
  float mq = __ldg(mask + q);
  __syncthreads();

  // Phase A: logits
  for (int k = t; k < N_; k += 256) {
    float mterm = INF_ * (mq * __ldg(mask + k) - 1.f);
    const float* bp = g_bias + ((size_t)q * N_ + k) * 12;
    float4 b0 = *(const float4*)bp;
    float4 b1 = *(const float4*)(bp + 4);
    float4 b2 = *(const float4*)(bp + 8);
    float bh[12] = {b0.x, b0.y, b0.z, b0.w, b1.x, b1.y, b1.z, b1.w, b2.x, b2.y, b2.z, b2.w};
#pragma unroll
    for (int h = 0; h < 12; ++h) {
      float d = 0.f;
#pragma unroll
      for (int c = 0; c < 16; ++c)
        d = fmaf(qh_s[h * 16 + c], __ldg(g_khT + (h * 16 + c) * N_ + k), d);
      float e = 0.f;
#pragma unroll
      for (int j = 0; j < 12; ++j)
        e = fmaf(qp_s[h * 12 + j], __ldg(g_kptsT + (h * 12 + j) * N_ + k), e);
      float k2 = __ldg(g_k2T + h * N_ + k);
      lgT[h][k] = bh[h] + d + c0_s[h] * (e - 0.5f * k2) + cb_s[h] + mterm;
    }
  }
  __syncthreads();

  // Phase B: softmax over k (warp per head)
  int wid = t >> 5, lid = t & 31;
  for (int h = wid; h < 12; h += 8) {
    float mx = -3.0e38f;
    for (int k = lid; k < N_; k += 32) mx = fmaxf(mx, lgT[h][k]);
#pragma unroll
    for (int o = 16; o > 0; o >>= 1) mx = fmaxf(mx, __shfl_xor_sync(0xffffffffu, mx, o));
    float sum = 0.f;
    for (int k = lid; k < N_; k += 32) {
      float w = __expf(0.57735026919f * (lgT[h][k] - mx));
      lgT[h][k] = w;
      sum += w;
    }
#pragma unroll
    for (int o = 16; o > 0; o >>= 1) sum += __shfl_xor_sync(0xffffffffu, sum, o);
    float inv = 1.f / sum;
    for (int k = lid; k < N_; k += 32) lgT[h][k] *= inv;
  }
  __syncthreads();

  // Phase C: o and o_pt (global frame)
  if (t < 240) {
    int h = t / 20, ci = (t % 20) * 2;
    const float* v0 = g_vcatT + (h * 40 + ci) * N_;
    float a0 = 0.f, a1 = 0.f;
    for (int k = 0; k < N_; k += 4) {
      float4 a4 = *(const float4*)&lgT[h][k];
      float4 x0 = *(const float4*)(v0 + k);
      float4 x1 = *(const float4*)(v0 + N_ + k);
      a0 += a4.x * x0.x + a4.y * x0.y + a4.z * x0.z + a4.w * x0.w;
      a1 += a4.x * x1.x + a4.y * x1.y + a4.z * x1.z + a4.w * x1.w;
    }
    if (ci < 16) g_cat[q * CATW + h * 16 + ci] = a0; else opt_s[h * 24 + ci - 16] = a0;
    if (ci + 1 < 16) g_cat[q * CATW + h * 16 + ci + 1] = a1; else opt_s[h * 24 + ci + 1 - 16] = a1;
  }
  __syncthreads();

  // Phase C2: inverse rigid + norms
  if (t < 96) {
    float R[9], tr[3];
#pragma unroll
    for (int j = 0; j < 9; ++j) R[j] = __ldg(rot + q * 9 + j);
#pragma unroll
    for (int j = 0; j < 3; ++j) tr[j] = __ldg(trans + q * 3 + j);
    int h = t >> 3, p = t & 7;
    float ex = opt_s[h * 24 + p * 3 + 0] - tr[0];
    float ey = opt_s[h * 24 + p * 3 + 1] - tr[1];
    float ez = opt_s[h * 24 + p * 3 + 2] - tr[2];
    float lx = R[0] * ex + R[3] * ey + R[6] * ez;
    float ly = R[1] * ex + R[4] * ey + R[7] * ez;
    float lz = R[2] * ex + R[5] * ey + R[8] * ez;
    float* cp = g_cat + q * CATW + 192;
    cp[t] = lx;
    cp[96 + t] = ly;
    cp[192 + t] = lz;
    cp[288 + t] = sqrtf(lx * lx + ly * ly + lz * lz + 1e-8f);
  }

  // Phase D: o_pair = a @ z[q]
  {
    int grp = t >> 7, c = t & 127;
    float acc[6] = {0.f, 0.f, 0.f, 0.f, 0.f, 0.f};
    const float* zq = z + (size_t)q * N_ * CZ + c;
    for (int k = 0; k < N_; k += 4) {
      float4 a4[6];
#pragma unroll
      for (int i = 0; i < 6; ++i) a4[i] = *(const float4*)&lgT[grp * 6 + i][k];
#pragma unroll
      for (int kk = 0; kk < 4; ++kk) {
        float zv = __ldg(zq + (size_t)(k + kk) * CZ);
#pragma unroll
        for (int i = 0; i < 6; ++i) acc[i] = fmaf((&a4[i].x)[kk], zv, acc[i]);
      }
    }
#pragma unroll
    for (int i = 0; i < 6; ++i)
      g_cat[q * CATW + 576 + (grp * 6 + i) * 128 + c] = acc[i];
  }
}

// ---------------- final add ----------------
__global__ void k_add(const float* __restrict__ bo, float* __restrict__ out) {
  int i = blockIdx.x * 256 + threadIdx.x;
  if (i < N_ * CS) {
    int col = i % CS;
    out[i] = g_part[0][i] + g_part[1][i] + g_part[2][i] + __ldg(bo + col);
  }
}

extern "C" void kernel_launch(void* const* d_in, const int* in_sizes, int n_in,
                              void* d_out, int out_size) {
  const float* s     = (const float*)d_in[0];
  const float* z     = (const float*)d_in[1];
  const float* rot   = (const float*)d_in[2];
  const float* trans = (const float*)d_in[3];
  const float* mask  = (const float*)d_in[4];
  const float* w_q   = (const float*)d_in[5];
  const float* b_q   = (const float*)d_in[6];
  const float* w_k   = (const float*)d_in[7];
  const float* b_k   = (const float*)d_in[8];
  const float* w_v   = (const float*)d_in[9];
  const float* b_v   = (const float*)d_in[10];
  const float* w_qp  = (const float*)d_in[11];
  const float* b_qp  = (const float*)d_in[12];
  const float* w_kp  = (const float*)d_in[13];
  const float* b_kp  = (const float*)d_in[14];
  const float* w_vp  = (const float*)d_in[15];
  const float* b_vp  = (const float*)d_in[16];
  const float* w_b   = (const float*)d_in[17];
  const float* b_b   = (const float*)d_in[18];
  const float* hw    = (const float*)d_in[19];
  const float* w_o   = (const float*)d_in[20];
  const float* b_o   = (const float*)d_in[21];
  float* out = (float*)d_out;

  k_pack<<<1728, 256>>>(w_q, w_k, w_v, w_qp, w_kp, w_vp,
                        b_q, b_k, b_v, b_qp, b_kp, b_vp, hw);
  k_gemm1<<<dim3(12, 18), 256>>>(s);
  k_proj<<<N_, 128>>>(rot, trans);
  k_bias<<<2304, 128>>>(z, w_b, b_b);
  k_attn<<<N_, 256>>>(z, mask, rot, trans);
  k_gemm2<<<dim3(12, 6, 3), 256>>>(w_o);
  k_add<<<1152, 256>>>(b_o, out);
}

// round 3
// speedup vs baseline: 1.5432x; 1.5432x over previous
#include <cuda_runtime.h>
#include <math.h>

#define N_ 768
#define CS 384
#define CZ 128
#define NH 12
#define LINW 1152
#define CATW 2112
#define INF_ 100000.0f
#define NK_ ((size_t)N_ * N_)   // 589824

// ---------------- device scratch ----------------
__device__ float g_wpack[CS * LINW];
__device__ float g_bpack[LINW];
__device__ float g_pw[NH];
__device__ float g_lin[N_ * LINW];
__device__ float g_qops[NH * N_ * 32];   // per (h,q): qh*0.25 [0:16), qpts [16:28), q2 [28]
__device__ float g_kops[NH * N_ * 32];   // per (h,k): kh, kpts, k2
__device__ float g_vops[NH * N_ * 40];   // per (h,k): v [0:16), vpts global [16:40)
__device__ float g_L[NH * NK_];          // bias -> attention weights (in place)
__device__ float g_cat[N_ * CATW];
__device__ float g_part[3][N_ * CS];

// ---------------- f32x2 helpers ----------------
__device__ __forceinline__ unsigned long long pk2(float a, float b) {
  unsigned long long r;
  asm("mov.b64 %0, {%1,%2};" : "=l"(r) : "f"(a), "f"(b));
  return r;
}
__device__ __forceinline__ void upk2(unsigned long long v, float& a, float& b) {
  asm("mov.b64 {%0,%1}, %2;" : "=f"(a), "=f"(b) : "l"(v));
}
__device__ __forceinline__ void fma2(unsigned long long& d, unsigned long long a,
                                     unsigned long long b) {
  asm("fma.rn.f32x2 %0, %1, %2, %0;" : "+l"(d) : "l"(a), "l"(b));
}

#define MM16(a, b, c)                                                                                   \
  c[0][0]=fmaf(a.x,b.x,c[0][0]); c[0][1]=fmaf(a.x,b.y,c[0][1]); c[0][2]=fmaf(a.x,b.z,c[0][2]); c[0][3]=fmaf(a.x,b.w,c[0][3]); \
  c[1][0]=fmaf(a.y,b.x,c[1][0]); c[1][1]=fmaf(a.y,b.y,c[1][1]); c[1][2]=fmaf(a.y,b.z,c[1][2]); c[1][3]=fmaf(a.y,b.w,c[1][3]); \
  c[2][0]=fmaf(a.z,b.x,c[2][0]); c[2][1]=fmaf(a.z,b.y,c[2][1]); c[2][2]=fmaf(a.z,b.z,c[2][2]); c[2][3]=fmaf(a.z,b.w,c[2][3]); \
  c[3][0]=fmaf(a.w,b.x,c[3][0]); c[3][1]=fmaf(a.w,b.y,c[3][1]); c[3][2]=fmaf(a.w,b.z,c[3][2]); c[3][3]=fmaf(a.w,b.w,c[3][3]);

// ---------------- pack weights ----------------
__global__ void k_pack(const float* wq, const float* wk, const float* wv,
                       const float* wqp, const float* wkp, const float* wvp,
                       const float* bq, const float* bk, const float* bv,
                       const float* bqp, const float* bkp, const float* bvp,
                       const float* hw) {
  int idx = blockIdx.x * 256 + threadIdx.x;
  if (idx < CS * LINW) {
    int i = idx / LINW, j = idx - i * LINW;
    float v;
    if (j < 192)       v = wq[i * 192 + j];
    else if (j < 384)  v = wk[i * 192 + j - 192];
    else if (j < 576)  v = wv[i * 192 + j - 384];
    else if (j < 720)  v = wqp[i * 144 + j - 576];
    else if (j < 864)  v = wkp[i * 144 + j - 720];
    else               v = wvp[i * 288 + j - 864];
    g_wpack[idx] = v;
  }
  if (idx < LINW) {
    int j = idx;
    float v;
    if (j < 192)       v = bq[j];
    else if (j < 384)  v = bk[j - 192];
    else if (j < 576)  v = bv[j - 384];
    else if (j < 720)  v = bqp[j - 576];
    else if (j < 864)  v = bkp[j - 720];
    else               v = bvp[j - 864];
    g_bpack[j] = v;
  }
  if (idx < NH) {
    float h = hw[idx];
    g_pw[idx] = 0.23570226039551584f * (fmaxf(h, 0.f) + log1pf(expf(-fabsf(h))));
  }
}

// ---------------- GEMM 1: g_lin = s @ wpack (768x1152, K=384) ----------------
__global__ __launch_bounds__(256) void k_gemm1(const float* __restrict__ A) {
  __shared__ float aT[16][68];
  __shared__ float bT[16][68];
  int m0 = blockIdx.x * 64, n0 = blockIdx.y * 64;
  int t = threadIdx.x;
  int mi = (t & 15) * 4, ni = (t >> 4) * 4;
  float c[4][4] = {};
  for (int kt = 0; kt < 24; ++kt) {
    int k0 = kt * 16;
    __syncthreads();
#pragma unroll
    for (int j = 0; j < 4; ++j) {
      int e = t + j * 256;
      aT[e & 15][e >> 4] = A[(m0 + (e >> 4)) * CS + k0 + (e & 15)];
      bT[e >> 6][e & 63] = g_wpack[(k0 + (e >> 6)) * LINW + n0 + (e & 63)];
    }
    __syncthreads();
#pragma unroll
    for (int kk = 0; kk < 16; ++kk) {
      float4 a = *(const float4*)&aT[kk][mi];
      float4 b = *(const float4*)&bT[kk][ni];
      MM16(a, b, c);
    }
  }
#pragma unroll
  for (int r = 0; r < 4; ++r)
#pragma unroll
    for (int cc = 0; cc < 4; ++cc)
      g_lin[(m0 + mi + r) * LINW + n0 + ni + cc] = c[r][cc];
}

// ---------------- GEMM 2: part[z] = cat @ w_o (768x384, K=2112 split 3) ----------------
__global__ __launch_bounds__(256) void k_gemm2(const float* __restrict__ B) {
  __shared__ float aT[16][68];
  __shared__ float bT[16][68];
  int m0 = blockIdx.x * 64, n0 = blockIdx.y * 64;
  int t = threadIdx.x;
  int mi = (t & 15) * 4, ni = (t >> 4) * 4;
  float c[4][4] = {};
  int kbase = blockIdx.z * 44 * 16;
  for (int kt = 0; kt < 44; ++kt) {
    int k0 = kbase + kt * 16;
    __syncthreads();
#pragma unroll
    for (int j = 0; j < 4; ++j) {
      int e = t + j * 256;
      aT[e & 15][e >> 4] = g_cat[(m0 + (e >> 4)) * CATW + k0 + (e & 15)];
      bT[e >> 6][e & 63] = B[(k0 + (e >> 6)) * CS + n0 + (e & 63)];
    }
    __syncthreads();
#pragma unroll
    for (int kk = 0; kk < 16; ++kk) {
      float4 a = *(const float4*)&aT[kk][mi];
      float4 b = *(const float4*)&bT[kk][ni];
      MM16(a, b, c);
    }
  }
  float* outp = &g_part[blockIdx.z][0];
#pragma unroll
  for (int r = 0; r < 4; ++r)
#pragma unroll
    for (int cc = 0; cc < 4; ++cc)
      outp[(m0 + mi + r) * CS + n0 + ni + cc] = c[r][cc];
}

// ---------------- projection epilogue per residue ----------------
__global__ __launch_bounds__(128) void k_proj(const float* __restrict__ rot,
                                              const float* __restrict__ trans) {
  __shared__ float s2[24];
  int q = blockIdx.x, t = threadIdx.x;
  const float* lin = g_lin + q * LINW;
  if (t < 24) s2[t] = 0.f;
  __syncthreads();
  float R[9], tr[3];
#pragma unroll
  for (int j = 0; j < 9; ++j) R[j] = __ldg(rot + q * 9 + j);
#pragma unroll
  for (int j = 0; j < 3; ++j) tr[j] = __ldg(trans + q * 3 + j);
  for (int i = t; i < 192; i += 128) {
    int h = i >> 4, c = i & 15;
    g_qops[(h * N_ + q) * 32 + c] = (lin[i] + g_bpack[i]) * 0.25f;
    g_kops[(h * N_ + q) * 32 + c] = lin[192 + i] + g_bpack[192 + i];
    g_vops[(h * N_ + q) * 40 + c] = lin[384 + i] + g_bpack[384 + i];
  }
  if (t < 96) {  // q/k points: lin layout [h][3][4]
    int which = t / 48;
    int i = t % 48;
    int h = i >> 2, p = i & 3;
    int base = 576 + which * 144 + h * 12;
    float lx = lin[base + p] + g_bpack[base + p];
    float ly = lin[base + 4 + p] + g_bpack[base + 4 + p];
    float lz = lin[base + 8 + p] + g_bpack[base + 8 + p];
    float gx = R[0] * lx + R[1] * ly + R[2] * lz + tr[0];
    float gy = R[3] * lx + R[4] * ly + R[5] * lz + tr[1];
    float gz = R[6] * lx + R[7] * ly + R[8] * lz + tr[2];
    float n2 = gx * gx + gy * gy + gz * gz;
    int o = (h * N_ + q) * 32 + 16 + p * 3;
    if (which == 0) {
      g_qops[o] = gx; g_qops[o + 1] = gy; g_qops[o + 2] = gz;
      atomicAdd(&s2[h], n2);
    } else {
      g_kops[o] = gx; g_kops[o + 1] = gy; g_kops[o + 2] = gz;
      atomicAdd(&s2[12 + h], n2);
    }
  }
  if (t < 96) {  // v points: lin layout [h][3][8]
    int h = t >> 3, p = t & 7;
    int base = 864 + h * 24;
    float lx = lin[base + p] + g_bpack[base + p];
    float ly = lin[base + 8 + p] + g_bpack[base + 8 + p];
    float lz = lin[base + 16 + p] + g_bpack[base + 16 + p];
    float gx = R[0] * lx + R[1] * ly + R[2] * lz + tr[0];
    float gy = R[3] * lx + R[4] * ly + R[5] * lz + tr[1];
    float gz = R[6] * lx + R[7] * ly + R[8] * lz + tr[2];
    int o = (h * N_ + q) * 40 + 16 + p * 3;
    g_vops[o] = gx; g_vops[o + 1] = gy; g_vops[o + 2] = gz;
  }
  __syncthreads();
  if (t < 12) {
    g_qops[(t * N_ + q) * 32 + 28] = s2[t];
    g_kops[(t * N_ + q) * 32 + 28] = s2[12 + t];
  }
}

// ---------------- pair bias: g_L[h][q*768+k] = z . w_b + b_b ----------------
// 512 rows per block, 128 threads x 4 rows, f32x2 packed FMA, DRAM-bound target.
__global__ __launch_bounds__(128) void k_bias2(const float* __restrict__ z,
                                               const float* __restrict__ wb,
                                               const float* __restrict__ bb) {
  __shared__ float zs[512 * 21];   // pad 21: conflict-free scalar column reads
  int t = threadIdx.x;
  size_t R0 = (size_t)blockIdx.x * 512;
  unsigned long long acc[2][12] = {};  // [pair][h]; pair0 = rows (t, t+128), pair1 = (t+256, t+384)
  for (int ch = 0; ch < 8; ++ch) {
    int c0 = ch * 16;
    __syncthreads();
#pragma unroll
    for (int i = 0; i < 16; ++i) {
      int idx = t + i * 128;
      int row = idx >> 2, f4 = idx & 3;
      float4 v = *(const float4*)(z + (R0 + row) * CZ + c0 + f4 * 4);
      float* d = zs + row * 21 + f4 * 4;
      d[0] = v.x; d[1] = v.y; d[2] = v.z; d[3] = v.w;
    }
    __syncthreads();
#pragma unroll
    for (int cc = 0; cc < 16; ++cc) {
      int c = c0 + cc;
      float4 w0 = __ldg((const float4*)(wb + c * 12));
      float4 w1 = __ldg((const float4*)(wb + c * 12 + 4));
      float4 w2 = __ldg((const float4*)(wb + c * 12 + 8));
      float wv[12] = {w0.x, w0.y, w0.z, w0.w, w1.x, w1.y, w1.z, w1.w,
                      w2.x, w2.y, w2.z, w2.w};
      float zA = zs[t * 21 + cc];
      float zB = zs[(t + 128) * 21 + cc];
      float zC = zs[(t + 256) * 21 + cc];
      float zD = zs[(t + 384) * 21 + cc];
      unsigned long long p0 = pk2(zA, zB), p1 = pk2(zC, zD);
#pragma unroll
      for (int h = 0; h < 12; ++h) {
        unsigned long long wd = pk2(wv[h], wv[h]);
        fma2(acc[0][h], p0, wd);
        fma2(acc[1][h], p1, wd);
      }
    }
  }
#pragma unroll
  for (int h = 0; h < 12; ++h) {
    float bbh = __ldg(bb + h);
    float a0, a1, a2, a3;
    upk2(acc[0][h], a0, a1);
    upk2(acc[1][h], a2, a3);
    float* Lp = g_L + (size_t)h * NK_ + R0;
    Lp[t] = a0 + bbh;
    Lp[t + 128] = a1 + bbh;
    Lp[t + 256] = a2 + bbh;
    Lp[t + 384] = a3 + bbh;
  }
}

// ---------------- logits + softmax (in place on g_L) ----------------
// block = (16 q) x (1 h); thread = (q, k-strip of 8); 96 logits in registers.
__global__ __launch_bounds__(128) void k_logits(const float* __restrict__ mask) {
  __shared__ float ks[256 * 36];
  int t = threadIdx.x;
  int h = blockIdx.y;
  int Q0 = blockIdx.x * 16;
  int ql = t >> 3, s = t & 7;
  int q = Q0 + ql;
  const float* qop = g_qops + ((size_t)h * N_ + q) * 32;
  float4 qh0 = *(const float4*)qop;
  float4 qh1 = *(const float4*)(qop + 4);
  float4 qh2 = *(const float4*)(qop + 8);
  float4 qh3 = *(const float4*)(qop + 12);
  float4 qp0 = *(const float4*)(qop + 16);
  float4 qp1 = *(const float4*)(qop + 20);
  float4 qp2 = *(const float4*)(qop + 24);
  float q2 = qop[28];
  float pw = g_pw[h];
  float cb = -0.5f * pw * q2;
  float mq = __ldg(mask + q);
  const float* Lrow = g_L + ((size_t)h * N_ + q) * N_;
  float lg[96];
#pragma unroll
  for (int ch = 0; ch < 3; ++ch) {
    int k0 = ch * 256;
    __syncthreads();
#pragma unroll
    for (int i = 0; i < 16; ++i) {
      int idx = t + i * 128;
      int row = idx >> 3, f4 = idx & 7;
      *(float4*)(ks + row * 36 + f4 * 4) =
          *(const float4*)(g_kops + ((size_t)h * N_ + k0 + row) * 32 + f4 * 4);
    }
    __syncthreads();
#pragma unroll
    for (int jj = 0; jj < 32; ++jj) {
      int kl = s + 8 * jj;
      const float* kr = ks + kl * 36;
      float4 k0v = *(const float4*)kr;
      float4 k1v = *(const float4*)(kr + 4);
      float4 k2v = *(const float4*)(kr + 8);
      float4 k3v = *(const float4*)(kr + 12);
      float4 p0 = *(const float4*)(kr + 16);
      float4 p1 = *(const float4*)(kr + 20);
      float4 p2 = *(const float4*)(kr + 24);
      float k2s = kr[28];
      float d = qh0.x * k0v.x + qh0.y * k0v.y + qh0.z * k0v.z + qh0.w * k0v.w
              + qh1.x * k1v.x + qh1.y * k1v.y + qh1.z * k1v.z + qh1.w * k1v.w
              + qh2.x * k2v.x + qh2.y * k2v.y + qh2.z * k2v.z + qh2.w * k2v.w
              + qh3.x * k3v.x + qh3.y * k3v.y + qh3.z * k3v.z + qh3.w * k3v.w;
      float e = qp0.x * p0.x + qp0.y * p0.y + qp0.z * p0.z + qp0.w * p0.w
              + qp1.x * p1.x + qp1.y * p1.y + qp1.z * p1.z + qp1.w * p1.w
              + qp2.x * p2.x + qp2.y * p2.y + qp2.z * p2.z + qp2.w * p2.w;
      int k = k0 + kl;
      float mk = __ldg(mask + k);
      lg[ch * 32 + jj] = Lrow[k] + d + pw * (e - 0.5f * k2s) + cb
                         + INF_ * (mq * mk - 1.f);
    }
  }
  // softmax over k (8 lanes per q)
  float mx = -3.0e38f;
#pragma unroll
  for (int i = 0; i < 96; ++i) mx = fmaxf(mx, lg[i]);
  mx = fmaxf(mx, __shfl_xor_sync(0xffffffffu, mx, 1));
  mx = fmaxf(mx, __shfl_xor_sync(0xffffffffu, mx, 2));
  mx = fmaxf(mx, __shfl_xor_sync(0xffffffffu, mx, 4));
  float sum = 0.f;
#pragma unroll
  for (int i = 0; i < 96; ++i) {
    float w = __expf(0.57735026919f * (lg[i] - mx));
    lg[i] = w;
    sum += w;
  }
  sum += __shfl_xor_sync(0xffffffffu, sum, 1);
  sum += __shfl_xor_sync(0xffffffffu, sum, 2);
  sum += __shfl_xor_sync(0xffffffffu, sum, 4);
  float inv = 1.f / sum;
  float* Lw = g_L + ((size_t)h * N_ + q) * N_;
#pragma unroll
  for (int ch = 0; ch < 3; ++ch)
#pragma unroll
    for (int jj = 0; jj < 32; ++jj)
      Lw[ch * 256 + s + 8 * jj] = lg[ch * 32 + jj] * inv;
}

// ---------------- o + o_pt + norms ----------------
// block = (32 q) x (1 h); 160 threads = 32 q x 5 strips of 8 dims.
__global__ __launch_bounds__(160) void k_out(const float* __restrict__ rot,
                                             const float* __restrict__ trans) {
  __shared__ float as[32 * 132];
  __shared__ float vs[128 * 44];
  __shared__ float os[32 * 40];
  int t = threadIdx.x;
  int h = blockIdx.y;
  int Q0 = blockIdx.x * 32;
  int q = t / 5, s = t - q * 5;
  float acc[8] = {};
  for (int ch = 0; ch < 6; ++ch) {
    int k0 = ch * 128;
    __syncthreads();
    for (int idx = t; idx < 1024; idx += 160) {
      int qq = idx >> 5, f4 = idx & 31;
      *(float4*)(as + qq * 132 + f4 * 4) =
          *(const float4*)(g_L + ((size_t)h * N_ + Q0 + qq) * N_ + k0 + f4 * 4);
    }
    for (int idx = t; idx < 1280; idx += 160) {
      int row = idx / 10, f4 = idx - row * 10;
      *(float4*)(vs + row * 44 + f4 * 4) =
          *(const float4*)(g_vops + ((size_t)h * N_ + k0 + row) * 40 + f4 * 4);
    }
    __syncthreads();
#pragma unroll 4
    for (int kl = 0; kl < 128; ++kl) {
      float a = as[q * 132 + kl];
      float4 v0 = *(const float4*)(vs + kl * 44 + 8 * s);
      float4 v1 = *(const float4*)(vs + kl * 44 + 8 * s + 4);
      acc[0] = fmaf(a, v0.x, acc[0]); acc[1] = fmaf(a, v0.y, acc[1]);
      acc[2] = fmaf(a, v0.z, acc[2]); acc[3] = fmaf(a, v0.w, acc[3]);
      acc[4] = fmaf(a, v1.x, acc[4]); acc[5] = fmaf(a, v1.y, acc[5]);
      acc[6] = fmaf(a, v1.z, acc[6]); acc[7] = fmaf(a, v1.w, acc[7]);
    }
  }
#pragma unroll
  for (int i = 0; i < 8; ++i) os[q * 40 + 8 * s + i] = acc[i];
  __syncthreads();
  for (int idx = t; idx < 512; idx += 160) {
    int qq = idx >> 4, c = idx & 15;
    g_cat[(size_t)(Q0 + qq) * CATW + h * 16 + c] = os[qq * 40 + c];
  }
  for (int idx = t; idx < 256; idx += 160) {
    int qq = idx >> 3, p = idx & 7;
    int gq = Q0 + qq;
    float ex = os[qq * 40 + 16 + 3 * p] - __ldg(trans + gq * 3 + 0);
    float ey = os[qq * 40 + 17 + 3 * p] - __ldg(trans + gq * 3 + 1);
    float ez = os[qq * 40 + 18 + 3 * p] - __ldg(trans + gq * 3 + 2);
    const float* R = rot + gq * 9;
    float lx = __ldg(R + 0) * ex + __ldg(R + 3) * ey + __ldg(R + 6) * ez;
    float ly = __ldg(R + 1) * ex + __ldg(R + 4) * ey + __ldg(R + 7) * ez;
    float lz = __ldg(R + 2) * ex + __ldg(R + 5) * ey + __ldg(R + 8) * ez;
    float* cp = g_cat + (size_t)gq * CATW + 192 + h * 8 + p;
    cp[0] = lx;
    cp[96] = ly;
    cp[192] = lz;
    cp[288] = sqrtf(lx * lx + ly * ly + lz * lz + 1e-8f);
  }
}

// ---------------- o_pair: per q, stream z once ----------------
__global__ __launch_bounds__(256) void k_opair(const float* __restrict__ z) {
  extern __shared__ float sm[];
  float* aT = sm;  // [768][20] transposed attention weights
  int t = threadIdx.x;
  int q = blockIdx.x;
#pragma unroll
  for (int h = 0; h < 12; ++h)
    for (int kk = t; kk < N_; kk += 256)
      aT[kk * 20 + h] = g_L[((size_t)h * N_ + q) * N_ + kk];
  __syncthreads();
  int c2 = (t & 63) * 2, kg = t >> 6;
  const float* zq = z + (size_t)q * N_ * CZ;
  unsigned long long acc[12] = {};
  for (int k = kg; k < N_; k += 4) {
    unsigned long long zd = *(const unsigned long long*)(zq + (size_t)k * CZ + c2);
    const float* ar = aT + k * 20;
    float4 a0 = *(const float4*)ar;
    float4 a1 = *(const float4*)(ar + 4);
    float4 a2 = *(const float4*)(ar + 8);
    float av[12] = {a0.x, a0.y, a0.z, a0.w, a1.x, a1.y, a1.z, a1.w,
                    a2.x, a2.y, a2.z, a2.w};
#pragma unroll
    for (int h = 0; h < 12; ++h) fma2(acc[h], zd, pk2(av[h], av[h]));
  }
  __syncthreads();
  unsigned long long* buf = (unsigned long long*)sm;  // [256][12]
#pragma unroll
  for (int h = 0; h < 12; ++h) buf[t * 12 + h] = acc[h];
  __syncthreads();
  for (int idx = t; idx < 1536; idx += 256) {
    int h = idx >> 7, c = idx & 127;
    float sum = 0.f;
#pragma unroll
    for (int g = 0; g < 4; ++g) {
      float lo, hi;
      upk2(buf[(g * 64 + (c >> 1)) * 12 + h], lo, hi);
      sum += (c & 1) ? hi : lo;
    }
    g_cat[(size_t)q * CATW + 576 + h * 128 + c] = sum;
  }
}

// ---------------- final add ----------------
__global__ void k_add(const float* __restrict__ bo, float* __restrict__ out) {
  int i = blockIdx.x * 256 + threadIdx.x;
  if (i < N_ * CS) {
    int col = i % CS;
    out[i] = g_part[0][i] + g_part[1][i] + g_part[2][i] + __ldg(bo + col);
  }
}

extern "C" void kernel_launch(void* const* d_in, const int* in_sizes, int n_in,
                              void* d_out, int out_size) {
  const float* s     = (const float*)d_in[0];
  const float* z     = (const float*)d_in[1];
  const float* rot   = (const float*)d_in[2];
  const float* trans = (const float*)d_in[3];
  const float* mask  = (const float*)d_in[4];
  const float* w_q   = (const float*)d_in[5];
  const float* b_q   = (const float*)d_in[6];
  const float* w_k   = (const float*)d_in[7];
  const float* b_k   = (const float*)d_in[8];
  const float* w_v   = (const float*)d_in[9];
  const float* b_v   = (const float*)d_in[10];
  const float* w_qp  = (const float*)d_in[11];
  const float* b_qp  = (const float*)d_in[12];
  const float* w_kp  = (const float*)d_in[13];
  const float* b_kp  = (const float*)d_in[14];
  const float* w_vp  = (const float*)d_in[15];
  const float* b_vp  = (const float*)d_in[16];
  const float* w_b   = (const float*)d_in[17];
  const float* b_b   = (const float*)d_in[18];
  const float* hw    = (const float*)d_in[19];
  const float* w_o   = (const float*)d_in[20];
  const float* b_o   = (const float*)d_in[21];
  float* out = (float*)d_out;

  static bool attr_done = false;
  if (!attr_done) {
    cudaFuncSetAttribute(k_opair, cudaFuncAttributeMaxDynamicSharedMemorySize, 65536);
    attr_done = true;
  }

  k_pack<<<1728, 256>>>(w_q, w_k, w_v, w_qp, w_kp, w_vp,
                        b_q, b_k, b_v, b_qp, b_kp, b_vp, hw);
  k_gemm1<<<dim3(12, 18), 256>>>(s);
  k_proj<<<N_, 128>>>(rot, trans);
  k_bias2<<<1152, 128>>>(z, w_b, b_b);
  k_logits<<<dim3(48, 12), 128>>>(mask);
  k_out<<<dim3(24, 12), 160>>>(rot, trans);
  k_opair<<<N_, 256, 768 * 20 * 4>>>(z);
  k_gemm2<<<dim3(12, 6, 3), 256>>>(w_o);
  k_add<<<1152, 256>>>(b_o, out);
}

// round 4
// speedup vs baseline: 1.6665x; 1.0799x over previous
#include <cuda_runtime.h>
#include <math.h>

#define N_ 768
#define CS 384
#define CZ 128
#define NH 12
#define LINW 1152
#define CATW 2112
#define INF_ 100000.0f
#define NK_ ((size_t)N_ * N_)   // 589824

// ---------------- device scratch ----------------
__device__ float g_wpack[CS * LINW];
__device__ float g_bpack[LINW];
__device__ float g_pw[NH];
__device__ float g_lin[N_ * LINW];
__device__ float g_qops[NH * N_ * 32];   // per (h,q): qh*0.25 [0:16), qpts [16:28), q2 [28]
__device__ float g_kops[NH * N_ * 32];   // per (h,k): kh, kpts, k2
__device__ float g_vops[NH * N_ * 40];   // per (h,k): v [0:16), vpts global [16:40)
__device__ float g_L[NH * NK_];          // bias -> attention weights (in place)
__device__ float g_cat[N_ * CATW];
__device__ float g_part[3][N_ * CS];

// ---------------- f32x2 helpers ----------------
typedef unsigned long long u64;
__device__ __forceinline__ u64 pk2(float a, float b) {
  u64 r;
  asm("mov.b64 %0, {%1,%2};" : "=l"(r) : "f"(a), "f"(b));
  return r;
}
__device__ __forceinline__ void upk2(u64 v, float& a, float& b) {
  asm("mov.b64 {%0,%1}, %2;" : "=f"(a), "=f"(b) : "l"(v));
}
__device__ __forceinline__ void fma2(u64& d, u64 a, u64 b) {
  asm("fma.rn.f32x2 %0, %1, %2, %0;" : "+l"(d) : "l"(a), "l"(b));
}

// ---------------- pack weights ----------------
__global__ void k_pack(const float* wq, const float* wk, const float* wv,
                       const float* wqp, const float* wkp, const float* wvp,
                       const float* bq, const float* bk, const float* bv,
                       const float* bqp, const float* bkp, const float* bvp,
                       const float* hw) {
  int idx = blockIdx.x * 256 + threadIdx.x;
  if (idx < CS * LINW) {
    int i = idx / LINW, j = idx - i * LINW;
    float v;
    if (j < 192)       v = wq[i * 192 + j];
    else if (j < 384)  v = wk[i * 192 + j - 192];
    else if (j < 576)  v = wv[i * 192 + j - 384];
    else if (j < 720)  v = wqp[i * 144 + j - 576];
    else if (j < 864)  v = wkp[i * 144 + j - 720];
    else               v = wvp[i * 288 + j - 864];
    g_wpack[idx] = v;
  }
  if (idx < LINW) {
    int j = idx;
    float v;
    if (j < 192)       v = bq[j];
    else if (j < 384)  v = bk[j - 192];
    else if (j < 576)  v = bv[j - 384];
    else if (j < 720)  v = bqp[j - 576];
    else if (j < 864)  v = bkp[j - 720];
    else               v = bvp[j - 864];
    g_bpack[j] = v;
  }
  if (idx < NH) {
    float h = hw[idx];
    g_pw[idx] = 0.23570226039551584f * (fmaxf(h, 0.f) + log1pf(expf(-fabsf(h))));
  }
}

// ---------------- GEMM 1: g_lin = s @ wpack (768x1152, K=384) ----------------
__global__ __launch_bounds__(256) void k_gemm1(const float* __restrict__ A) {
  __shared__ float aT[16][68];
  __shared__ float bT[16][68];
  int m0 = blockIdx.x * 64, n0 = blockIdx.y * 64;
  int t = threadIdx.x;
  int mi = (t & 15) * 4, ni = (t >> 4) * 4;
  u64 c2[4][2] = {};
  for (int kt = 0; kt < 24; ++kt) {
    int k0 = kt * 16;
    __syncthreads();
#pragma unroll
    for (int j = 0; j < 4; ++j) {
      int e = t + j * 256;
      aT[e & 15][e >> 4] = A[(m0 + (e >> 4)) * CS + k0 + (e & 15)];
      bT[e >> 6][e & 63] = g_wpack[(k0 + (e >> 6)) * LINW + n0 + (e & 63)];
    }
    __syncthreads();
#pragma unroll
    for (int kk = 0; kk < 16; ++kk) {
      float4 a = *(const float4*)&aT[kk][mi];
      float4 b = *(const float4*)&bT[kk][ni];
      u64 b0 = pk2(b.x, b.y), b1 = pk2(b.z, b.w);
      u64 a0 = pk2(a.x, a.x), a1 = pk2(a.y, a.y), a2 = pk2(a.z, a.z), a3 = pk2(a.w, a.w);
      fma2(c2[0][0], a0, b0); fma2(c2[0][1], a0, b1);
      fma2(c2[1][0], a1, b0); fma2(c2[1][1], a1, b1);
      fma2(c2[2][0], a2, b0); fma2(c2[2][1], a2, b1);
      fma2(c2[3][0], a3, b0); fma2(c2[3][1], a3, b1);
    }
  }
#pragma unroll
  for (int r = 0; r < 4; ++r)
#pragma unroll
    for (int j = 0; j < 2; ++j) {
      float lo, hi;
      upk2(c2[r][j], lo, hi);
      g_lin[(m0 + mi + r) * LINW + n0 + ni + 2 * j] = lo;
      g_lin[(m0 + mi + r) * LINW + n0 + ni + 2 * j + 1] = hi;
    }
}

// ---------------- GEMM 2: part[z] = cat @ w_o (768x384, K=2112 split 3) ----------------
__global__ __launch_bounds__(256) void k_gemm2(const float* __restrict__ B) {
  __shared__ float aT[16][68];
  __shared__ float bT[16][68];
  int m0 = blockIdx.x * 64, n0 = blockIdx.y * 64;
  int t = threadIdx.x;
  int mi = (t & 15) * 4, ni = (t >> 4) * 4;
  u64 c2[4][2] = {};
  int kbase = blockIdx.z * 44 * 16;
  for (int kt = 0; kt < 44; ++kt) {
    int k0 = kbase + kt * 16;
    __syncthreads();
#pragma unroll
    for (int j = 0; j < 4; ++j) {
      int e = t + j * 256;
      aT[e & 15][e >> 4] = g_cat[(m0 + (e >> 4)) * CATW + k0 + (e & 15)];
      bT[e >> 6][e & 63] = B[(k0 + (e >> 6)) * CS + n0 + (e & 63)];
    }
    __syncthreads();
#pragma unroll
    for (int kk = 0; kk < 16; ++kk) {
      float4 a = *(const float4*)&aT[kk][mi];
      float4 b = *(const float4*)&bT[kk][ni];
      u64 b0 = pk2(b.x, b.y), b1 = pk2(b.z, b.w);
      u64 a0 = pk2(a.x, a.x), a1 = pk2(a.y, a.y), a2 = pk2(a.z, a.z), a3 = pk2(a.w, a.w);
      fma2(c2[0][0], a0, b0); fma2(c2[0][1], a0, b1);
      fma2(c2[1][0], a1, b0); fma2(c2[1][1], a1, b1);
      fma2(c2[2][0], a2, b0); fma2(c2[2][1], a2, b1);
      fma2(c2[3][0], a3, b0); fma2(c2[3][1], a3, b1);
    }
  }
  float* outp = &g_part[blockIdx.z][0];
#pragma unroll
  for (int r = 0; r < 4; ++r)
#pragma unroll
    for (int j = 0; j < 2; ++j) {
      float lo, hi;
      upk2(c2[r][j], lo, hi);
      outp[(m0 + mi + r) * CS + n0 + ni + 2 * j] = lo;
      outp[(m0 + mi + r) * CS + n0 + ni + 2 * j + 1] = hi;
    }
}

// ---------------- projection epilogue per residue ----------------
__global__ __launch_bounds__(128) void k_proj(const float* __restrict__ rot,
                                              const float* __restrict__ trans) {
  __shared__ float s2[24];
  int q = blockIdx.x, t = threadIdx.x;
  const float* lin = g_lin + q * LINW;
  if (t < 24) s2[t] = 0.f;
  __syncthreads();
  float R[9], tr[3];
#pragma unroll
  for (int j = 0; j < 9; ++j) R[j] = __ldg(rot + q * 9 + j);
#pragma unroll
  for (int j = 0; j < 3; ++j) tr[j] = __ldg(trans + q * 3 + j);
  for (int i = t; i < 192; i += 128) {
    int h = i >> 4, c = i & 15;
    g_qops[(h * N_ + q) * 32 + c] = (lin[i] + g_bpack[i]) * 0.25f;
    g_kops[(h * N_ + q) * 32 + c] = lin[192 + i] + g_bpack[192 + i];
    g_vops[(h * N_ + q) * 40 + c] = lin[384 + i] + g_bpack[384 + i];
  }
  if (t < 96) {  // q/k points: lin layout [h][3][4]
    int which = t / 48;
    int i = t % 48;
    int h = i >> 2, p = i & 3;
    int base = 576 + which * 144 + h * 12;
    float lx = lin[base + p] + g_bpack[base + p];
    float ly = lin[base + 4 + p] + g_bpack[base + 4 + p];
    float lz = lin[base + 8 + p] + g_bpack[base + 8 + p];
    float gx = R[0] * lx + R[1] * ly + R[2] * lz + tr[0];
    float gy = R[3] * lx + R[4] * ly + R[5] * lz + tr[1];
    float gz = R[6] * lx + R[7] * ly + R[8] * lz + tr[2];
    float n2 = gx * gx + gy * gy + gz * gz;
    int o = (h * N_ + q) * 32 + 16 + p * 3;
    if (which == 0) {
      g_qops[o] = gx; g_qops[o + 1] = gy; g_qops[o + 2] = gz;
      atomicAdd(&s2[h], n2);
    } else {
      g_kops[o] = gx; g_kops[o + 1] = gy; g_kops[o + 2] = gz;
      atomicAdd(&s2[12 + h], n2);
    }
  }
  if (t < 96) {  // v points: lin layout [h][3][8]
    int h = t >> 3, p = t & 7;
    int base = 864 + h * 24;
    float lx = lin[base + p] + g_bpack[base + p];
    float ly = lin[base + 8 + p] + g_bpack[base + 8 + p];
    float lz = lin[base + 16 + p] + g_bpack[base + 16 + p];
    float gx = R[0] * lx + R[1] * ly + R[2] * lz + tr[0];
    float gy = R[3] * lx + R[4] * ly + R[5] * lz + tr[1];
    float gz = R[6] * lx + R[7] * ly + R[8] * lz + tr[2];
    int o = (h * N_ + q) * 40 + 16 + p * 3;
    g_vops[o] = gx; g_vops[o + 1] = gy; g_vops[o + 2] = gz;
  }
  __syncthreads();
  if (t < 12) {
    g_qops[(t * N_ + q) * 32 + 28] = s2[t];
    g_kops[(t * N_ + q) * 32 + 28] = s2[12 + t];
  }
}

// ---------------- pair bias: g_L[h][row] = z[row] . w_b[:,h] + b_b[h] ----------------
// Thread = 2 rows; f32x2 lanes = (even cols, odd cols); w pairs broadcast from 6KB smem.
__global__ __launch_bounds__(256) void k_bias3(const float* __restrict__ z,
                                               const float* __restrict__ wb,
                                               const float* __restrict__ bb) {
  __shared__ u64 w2[64 * 12];
  int t = threadIdx.x;
  for (int idx = t; idx < 768; idx += 256) {
    int cp = idx / 12, h = idx - cp * 12;
    w2[cp * 12 + h] = pk2(__ldg(wb + (2 * cp) * 12 + h), __ldg(wb + (2 * cp + 1) * 12 + h));
  }
  __syncthreads();
  size_t rowA = (size_t)blockIdx.x * 512 + t;
  size_t rowB = rowA + 256;
  const float4* zA = (const float4*)(z + rowA * CZ);
  const float4* zB = (const float4*)(z + rowB * CZ);
  u64 accA[12] = {}, accB[12] = {};
#pragma unroll 8
  for (int c4 = 0; c4 < 32; ++c4) {
    float4 vA = zA[c4];
    float4 vB = zB[c4];
    u64 pA0 = pk2(vA.x, vA.y), pA1 = pk2(vA.z, vA.w);
    u64 pB0 = pk2(vB.x, vB.y), pB1 = pk2(vB.z, vB.w);
    const u64* wr0 = w2 + (2 * c4) * 12;
    const u64* wr1 = w2 + (2 * c4 + 1) * 12;
#pragma unroll
    for (int h = 0; h < 12; ++h) {
      u64 w0 = wr0[h], w1 = wr1[h];
      fma2(accA[h], pA0, w0);
      fma2(accB[h], pB0, w0);
      fma2(accA[h], pA1, w1);
      fma2(accB[h], pB1, w1);
    }
  }
#pragma unroll
  for (int h = 0; h < 12; ++h) {
    float bbh = __ldg(bb + h);
    float a0, a1, b0, b1;
    upk2(accA[h], a0, a1);
    upk2(accB[h], b0, b1);
    float* Lp = g_L + (size_t)h * NK_;
    Lp[rowA] = a0 + a1 + bbh;
    Lp[rowB] = b0 + b1 + bbh;
  }
}

// ---------------- logits + softmax (in place on g_L) ----------------
// block = (16 q) x (1 h); 256 threads; thread = (q, k-strip of 16); 48 logits in regs.
__global__ __launch_bounds__(256) void k_logits(const float* __restrict__ mask) {
  __shared__ float ks[256 * 36];
  int t = threadIdx.x;
  int h = blockIdx.y;
  int Q0 = blockIdx.x * 16;
  int ql = t >> 4, s = t & 15;
  int q = Q0 + ql;
  const float* qop = g_qops + ((size_t)h * N_ + q) * 32;
  const u64* qop8 = (const u64*)qop;
  u64 qh_u[8], qp_u[6];
#pragma unroll
  for (int i = 0; i < 8; ++i) qh_u[i] = qop8[i];
#pragma unroll
  for (int i = 0; i < 6; ++i) qp_u[i] = qop8[8 + i];
  float q2 = qop[28];
  float pw = g_pw[h];
  float cb = -0.5f * pw * q2;
  float mq = __ldg(mask + q);
  const float* Lrow = g_L + ((size_t)h * N_ + q) * N_;
  float lg[48];
#pragma unroll
  for (int ch = 0; ch < 3; ++ch) {
    int k0 = ch * 256;
    __syncthreads();
#pragma unroll
    for (int i = 0; i < 8; ++i) {
      int idx = t + i * 256;
      int row = idx >> 3, f4 = idx & 7;
      *(float4*)(ks + row * 36 + f4 * 4) =
          *(const float4*)(g_kops + ((size_t)h * N_ + k0 + row) * 32 + f4 * 4);
    }
    __syncthreads();
#pragma unroll
    for (int jj = 0; jj < 16; ++jj) {
      int kl = s + 16 * jj;
      const u64* kr8 = (const u64*)(ks + kl * 36);
      u64 d2 = 0, e2 = 0;
#pragma unroll
      for (int i = 0; i < 8; ++i) fma2(d2, kr8[i], qh_u[i]);
#pragma unroll
      for (int i = 0; i < 6; ++i) fma2(e2, kr8[8 + i], qp_u[i]);
      float dlo, dhi, elo, ehi;
      upk2(d2, dlo, dhi);
      upk2(e2, elo, ehi);
      float k2s = ks[kl * 36 + 28];
      int k = k0 + kl;
      lg[ch * 16 + jj] = Lrow[k] + dlo + dhi + pw * (elo + ehi - 0.5f * k2s) + cb
                         + INF_ * (mq * __ldg(mask + k) - 1.f);
    }
  }
  // softmax over k (16 lanes per q)
  float mx = -3.0e38f;
#pragma unroll
  for (int i = 0; i < 48; ++i) mx = fmaxf(mx, lg[i]);
  mx = fmaxf(mx, __shfl_xor_sync(0xffffffffu, mx, 1));
  mx = fmaxf(mx, __shfl_xor_sync(0xffffffffu, mx, 2));
  mx = fmaxf(mx, __shfl_xor_sync(0xffffffffu, mx, 4));
  mx = fmaxf(mx, __shfl_xor_sync(0xffffffffu, mx, 8));
  float sum = 0.f;
#pragma unroll
  for (int i = 0; i < 48; ++i) {
    float w = __expf(0.57735026919f * (lg[i] - mx));
    lg[i] = w;
    sum += w;
  }
  sum += __shfl_xor_sync(0xffffffffu, sum, 1);
  sum += __shfl_xor_sync(0xffffffffu, sum, 2);
  sum += __shfl_xor_sync(0xffffffffu, sum, 4);
  sum += __shfl_xor_sync(0xffffffffu, sum, 8);
  float inv = 1.f / sum;
  float* Lw = g_L + ((size_t)h * N_ + q) * N_;
#pragma unroll
  for (int ch = 0; ch < 3; ++ch)
#pragma unroll
    for (int jj = 0; jj < 16; ++jj)
      Lw[ch * 256 + s + 16 * jj] = lg[ch * 16 + jj] * inv;
}

// ---------------- o + o_pt + norms ----------------
// block = (32 q) x (1 h); 160 threads = 32 q x 5 strips of 8 dims.
__global__ __launch_bounds__(160) void k_out(const float* __restrict__ rot,
                                             const float* __restrict__ trans) {
  __shared__ float as[32 * 132];
  __shared__ float vs[128 * 44];
  __shared__ float os[32 * 40];
  int t = threadIdx.x;
  int h = blockIdx.y;
  int Q0 = blockIdx.x * 32;
  int q = t / 5, s = t - q * 5;
  u64 acc2[4] = {};
  for (int ch = 0; ch < 6; ++ch) {
    int k0 = ch * 128;
    __syncthreads();
    for (int idx = t; idx < 1024; idx += 160) {
      int qq = idx >> 5, f4 = idx & 31;
      *(float4*)(as + qq * 132 + f4 * 4) =
          *(const float4*)(g_L + ((size_t)h * N_ + Q0 + qq) * N_ + k0 + f4 * 4);
    }
    for (int idx = t; idx < 1280; idx += 160) {
      int row = idx / 10, f4 = idx - row * 10;
      *(float4*)(vs + row * 44 + f4 * 4) =
          *(const float4*)(g_vops + ((size_t)h * N_ + k0 + row) * 40 + f4 * 4);
    }
    __syncthreads();
#pragma unroll 4
    for (int kl = 0; kl < 128; ++kl) {
      float a = as[q * 132 + kl];
      u64 au = pk2(a, a);
      const u64* vp = (const u64*)(vs + kl * 44 + 8 * s);
      fma2(acc2[0], vp[0], au);
      fma2(acc2[1], vp[1], au);
      fma2(acc2[2], vp[2], au);
      fma2(acc2[3], vp[3], au);
    }
  }
#pragma unroll
  for (int i = 0; i < 4; ++i) {
    float lo, hi;
    upk2(acc2[i], lo, hi);
    os[q * 40 + 8 * s + 2 * i] = lo;
    os[q * 40 + 8 * s + 2 * i + 1] = hi;
  }
  __syncthreads();
  for (int idx = t; idx < 512; idx += 160) {
    int qq = idx >> 4, c = idx & 15;
    g_cat[(size_t)(Q0 + qq) * CATW + h * 16 + c] = os[qq * 40 + c];
  }
  for (int idx = t; idx < 256; idx += 160) {
    int qq = idx >> 3, p = idx & 7;
    int gq = Q0 + qq;
    float ex = os[qq * 40 + 16 + 3 * p] - __ldg(trans + gq * 3 + 0);
    float ey = os[qq * 40 + 17 + 3 * p] - __ldg(trans + gq * 3 + 1);
    float ez = os[qq * 40 + 18 + 3 * p] - __ldg(trans + gq * 3 + 2);
    const float* R = rot + gq * 9;
    float lx = __ldg(R + 0) * ex + __ldg(R + 3) * ey + __ldg(R + 6) * ez;
    float ly = __ldg(R + 1) * ex + __ldg(R + 4) * ey + __ldg(R + 7) * ez;
    float lz = __ldg(R + 2) * ex + __ldg(R + 5) * ey + __ldg(R + 8) * ez;
    float* cp = g_cat + (size_t)gq * CATW + 192 + h * 8 + p;
    cp[0] = lx;
    cp[96] = ly;
    cp[192] = lz;
    cp[288] = sqrtf(lx * lx + ly * ly + lz * lz + 1e-8f);
  }
}

// ---------------- o_pair: per q, stream z once ----------------
__global__ __launch_bounds__(256) void k_opair(const float* __restrict__ z) {
  extern __shared__ float sm[];
  float* aT = sm;  // [768][20] transposed attention weights
  int t = threadIdx.x;
  int q = blockIdx.x;
#pragma unroll
  for (int h = 0; h < 12; ++h)
    for (int kk = t; kk < N_; kk += 256)
      aT[kk * 20 + h] = g_L[((size_t)h * N_ + q) * N_ + kk];
  __syncthreads();
  int c2 = (t & 63) * 2, kg = t >> 6;
  const float* zq = z + (size_t)q * N_ * CZ;
  u64 acc[12] = {};
  for (int k = kg; k < N_; k += 4) {
    u64 zd = *(const u64*)(zq + (size_t)k * CZ + c2);
    const float* ar = aT + k * 20;
    float4 a0 = *(const float4*)ar;
    float4 a1 = *(const float4*)(ar + 4);
    float4 a2 = *(const float4*)(ar + 8);
    float av[12] = {a0.x, a0.y, a0.z, a0.w, a1.x, a1.y, a1.z, a1.w,
                    a2.x, a2.y, a2.z, a2.w};
#pragma unroll
    for (int h = 0; h < 12; ++h) fma2(acc[h], zd, pk2(av[h], av[h]));
  }
  __syncthreads();
  u64* buf = (u64*)sm;  // [256][12]
#pragma unroll
  for (int h = 0; h < 12; ++h) buf[t * 12 + h] = acc[h];
  __syncthreads();
  for (int idx = t; idx < 1536; idx += 256) {
    int h = idx >> 7, c = idx & 127;
    float sum = 0.f;
#pragma unroll
    for (int g = 0; g < 4; ++g) {
      float lo, hi;
      upk2(buf[(g * 64 + (c >> 1)) * 12 + h], lo, hi);
      sum += (c & 1) ? hi : lo;
    }
    g_cat[(size_t)q * CATW + 576 + h * 128 + c] = sum;
  }
}

// ---------------- final add ----------------
__global__ void k_add(const float* __restrict__ bo, float* __restrict__ out) {
  int i = blockIdx.x * 256 + threadIdx.x;
  if (i < N_ * CS) {
    int col = i % CS;
    out[i] = g_part[0][i] + g_part[1][i] + g_part[2][i] + __ldg(bo + col);
  }
}

extern "C" void kernel_launch(void* const* d_in, const int* in_sizes, int n_in,
                              void* d_out, int out_size) {
  const float* s     = (const float*)d_in[0];
  const float* z     = (const float*)d_in[1];
  const float* rot   = (const float*)d_in[2];
  const float* trans = (const float*)d_in[3];
  const float* mask  = (const float*)d_in[4];
  const float* w_q   = (const float*)d_in[5];
  const float* b_q   = (const float*)d_in[6];
  const float* w_k   = (const float*)d_in[7];
  const float* b_k   = (const float*)d_in[8];
  const float* w_v   = (const float*)d_in[9];
  const float* b_v   = (const float*)d_in[10];
  const float* w_qp  = (const float*)d_in[11];
  const float* b_qp  = (const float*)d_in[12];
  const float* w_kp  = (const float*)d_in[13];
  const float* b_kp  = (const float*)d_in[14];
  const float* w_vp  = (const float*)d_in[15];
  const float* b_vp  = (const float*)d_in[16];
  const float* w_b   = (const float*)d_in[17];
  const float* b_b   = (const float*)d_in[18];
  const float* hw    = (const float*)d_in[19];
  const float* w_o   = (const float*)d_in[20];
  const float* b_o   = (const float*)d_in[21];
  float* out = (float*)d_out;

  static bool attr_done = false;
  if (!attr_done) {
    cudaFuncSetAttribute(k_opair, cudaFuncAttributeMaxDynamicSharedMemorySize, 65536);
    attr_done = true;
  }

  k_pack<<<1728, 256>>>(w_q, w_k, w_v, w_qp, w_kp, w_vp,
                        b_q, b_k, b_v, b_qp, b_kp, b_vp, hw);
  k_gemm1<<<dim3(12, 18), 256>>>(s);
  k_proj<<<N_, 128>>>(rot, trans);
  k_bias3<<<1152, 256>>>(z, w_b, b_b);
  k_logits<<<dim3(48, 12), 256>>>(mask);
  k_out<<<dim3(24, 12), 160>>>(rot, trans);
  k_opair<<<N_, 256, 768 * 20 * 4>>>(z);
  k_gemm2<<<dim3(12, 6, 3), 256>>>(w_o);
  k_add<<<1152, 256>>>(b_o, out);
}